// round 13
// baseline (speedup 1.0000x reference)
#include <cuda_runtime.h>
#include <cuda_fp16.h>
#include <cstdint>

// ---------------------------------------------------------------------------
// R13 (= R12 resubmit after infra failure): R11 + B fragments via
//      ldmatrix.x4.trans (half the B LDSM, identical values/order) +
//      tick_kernel so ncu slot 6 captures conv1 (launch period 3 -> 4).
//      conv2 = proven R4 fp32 FFMA2 kernel.
// ---------------------------------------------------------------------------

#define IMG   256
#define NB    8
#define CIN   64

__device__ float  g_h[NB * CIN * IMG * IMG];
__device__ __half g_w1h[9 * 64 * 64];          // [tap][c][oc] linear
__device__ float  g_w2q[CIN * 9 * 4];

__device__ __forceinline__ uint32_t smem_u32(const void* p) {
    uint32_t a;
    asm("{ .reg .u64 t; cvta.to.shared.u64 t, %1; cvt.u32.u64 %0, t; }"
        : "=r"(a) : "l"(p));
    return a;
}
__device__ __forceinline__ void ldsm4(uint32_t* r, uint32_t addr) {
    asm volatile("ldmatrix.sync.aligned.m8n8.x4.shared.b16 {%0,%1,%2,%3}, [%4];"
        : "=r"(r[0]), "=r"(r[1]), "=r"(r[2]), "=r"(r[3]) : "r"(addr));
}
__device__ __forceinline__ void ldsm4t(uint32_t* r, uint32_t addr) {
    asm volatile("ldmatrix.sync.aligned.m8n8.x4.trans.shared.b16 {%0,%1,%2,%3}, [%4];"
        : "=r"(r[0]), "=r"(r[1]), "=r"(r[2]), "=r"(r[3]) : "r"(addr));
}
__device__ __forceinline__ void mma16816(float* c, const uint32_t* a, const uint32_t* b) {
    asm volatile("mma.sync.aligned.m16n8k16.row.col.f32.f16.f16.f32 "
        "{%0,%1,%2,%3}, {%4,%5,%6,%7}, {%8,%9}, {%0,%1,%2,%3};"
        : "+f"(c[0]), "+f"(c[1]), "+f"(c[2]), "+f"(c[3])
        : "r"(a[0]), "r"(a[1]), "r"(a[2]), "r"(a[3]), "r"(b[0]), "r"(b[1]));
}
__device__ __forceinline__ void cp16(uint32_t dst, const void* src) {
    asm volatile("cp.async.cg.shared.global [%0], [%1], 16;"
        :: "r"(dst), "l"(src));
}
#define CP_COMMIT() asm volatile("cp.async.commit_group;" ::: "memory")
#define CP_WAIT0()  asm volatile("cp.async.wait_group 0;"  ::: "memory")

// dynamic smem layout:
#define A_TERMB 18720u                 // 130 rows x 144B per split term
#define W_OFF   37440u
#define W_BUF   9216u
#define P_OFF   (W_OFF + 2u * W_BUF)   // 55872
#define SMEM1   (P_OFF + 1024u)        // 56896 -> occ 3 (170.7KB)

// ---------------- prequant (one-shot) ---------------------------------------
__global__ void prequant_kernel(const float* __restrict__ w1,
                                const float* __restrict__ sw1,
                                const float* __restrict__ w2,
                                const float* __restrict__ sw2)
{
    int idx = blockIdx.x * 256 + threadIdx.x;
    if (idx < 9 * 64 * 64) {
        int oc  = idx & 63;
        int c   = (idx >> 6) & 63;
        int tap = idx >> 12;
        float w = w1[(oc * 64 + c) * 9 + tap];
        float s = sw1[oc];
        float q = rintf(w / s);
        q = fminf(fmaxf(q, -64.f), 63.f);
        g_w1h[idx] = __float2half_rn(q);        // exact 7-bit integer
    } else if (idx < 9 * 64 * 64 + 64 * 9 * 4) {
        int j  = idx - 9 * 64 * 64;
        int oc = j & 3;
        int k  = j >> 2;
        int c  = k / 9;
        int kk = k - c * 9;
        float v = 0.f;
        if (oc < 3) {
            float w = w2[(oc * CIN + c) * 9 + kk];
            float s = sw2[oc];
            float q = rintf(w / s);
            q = fminf(fmaxf(q, -64.f), 63.f);
            v = q * s;
        }
        g_w2q[j] = v;
    }
}

// tiny no-op: shifts ncu's captured launch slot onto conv1 (period 3 -> 4)
__global__ void tick_kernel() {}

// ---------------- conv1: HMMA, occ 3, x4 B loads -----------------------------
// CTA = 128-px row strip (n, y, x0), 64 oc. 256 thr = 8 warps.
// Warp tile: 32 px (mrow=(w&3)*32) x 32 oc (ncol=(w>>2)*32).
__global__ __launch_bounds__(256, 3)
void conv1_mma_kernel(const float* __restrict__ x,
                      const float* __restrict__ sw1,
                      const float* __restrict__ b1,
                      const float* __restrict__ alpha1,
                      const float* __restrict__ sa1)
{
    extern __shared__ unsigned char sm[];
    __half* s_a   = (__half*)sm;
    float*  s_prm = (float*)(sm + P_OFF);
    const uint32_t sa_base = smem_u32(sm);
    const uint32_t sw_base = sa_base + W_OFF;

    const int tid  = threadIdx.x;
    const int lane = tid & 31;
    const int warp = tid >> 5;
    const int mrow = (warp & 3) * 32;
    const int ncol = (warp >> 2) * 32;

    const int bid = blockIdx.x;          // 8n * 256y * 2xt = 4096
    const int x0  = (bid & 1) * 128;
    const int y   = (bid >> 1) & 255;
    const int n   = bid >> 9;

    // ---- prefetch W tap 0 via cp.async (overlaps params + A build) ----
    {
        const char* src = (const char*)g_w1h;
        uint32_t dst = sw_base + (uint32_t)(tid >> 3) * 144u
                     + (uint32_t)(tid & 7) * 16u;
        cp16(dst, src + tid * 16);
        cp16(dst + (256 >> 3) * 144u, src + (tid + 256) * 16);
        CP_COMMIT();
    }

    if (tid < 256) {
        int a = tid >> 6, oc = tid & 63;
        const float* src = (a == 0) ? sw1 : (a == 1) ? b1 : (a == 2) ? alpha1 : sa1;
        s_prm[a * 64 + oc] = src[oc];
    }

    float acc[2][4][4];
    #pragma unroll
    for (int i = 0; i < 2; ++i)
        #pragma unroll
        for (int j = 0; j < 4; ++j)
            #pragma unroll
            for (int k = 0; k < 4; ++k) acc[i][j][k] = 0.f;

    const uint32_t arow  = lane & 15;
    const uint32_t ahalf = (lane >> 4) * 16;
    // B x4 addressing: lanes 0-15 -> k-rows (this nb), lanes 16-31 -> nb+1
    const uint32_t bcol  = ((uint32_t)ncol + ((uint32_t)(lane >> 4) << 3)) * 2u;

    for (int s = 0; s < 3; ++s) {
        const int gy = y + s - 1;
        const bool row_ok = (unsigned)gy < 256u;
        if (s) __syncthreads();            // prior tap's A reads done
        // ---- build exact fp16 2-term split strip (144B rows) ----
        for (int idx = tid; idx < 64 * 130; idx += 256) {
            int c = idx / 130;
            int j = idx - c * 130;
            int gx = x0 - 1 + j;
            float v = 0.f;
            if (row_ok && (unsigned)gx < 256u)
                v = x[(((n * 64 + c) * 256 + gy) << 8) + gx];
            __half hi = __float2half_rn(v);
            __half lo = __float2half_rn(v - __half2float(hi));
            s_a[j * 72 + c]        = hi;
            s_a[9360 + j * 72 + c] = lo;   // 9360 halves = A_TERMB bytes
        }

        for (int kw = 0; kw < 3; ++kw) {
            const int tap = s * 3 + kw;
            CP_WAIT0();                    // W[tap] landed in buf[tap&1]
            __syncthreads();               // W (+A on kw==0) visible to all
            if (tap < 8) {                 // prefetch next tap into other buf
                const char* src = (const char*)g_w1h + (tap + 1) * 8192;
                uint32_t dst = sw_base + ((uint32_t)(tap + 1) & 1u) * W_BUF
                             + (uint32_t)(tid >> 3) * 144u
                             + (uint32_t)(tid & 7) * 16u;
                cp16(dst, src + tid * 16);
                cp16(dst + (256 >> 3) * 144u, src + (tid + 256) * 16);
                CP_COMMIT();
            }
            const uint32_t swb = sw_base + ((uint32_t)tap & 1u) * W_BUF;

            // per-accumulator order: t0:k0..k3, t1:k0..k3  (== R11 exactly)
            #pragma unroll
            for (int t = 0; t < 2; ++t) {
                #pragma unroll
                for (int k = 0; k < 4; ++k) {
                    uint32_t bf[4][2];
                    uint32_t brow = swb + (uint32_t)(k * 16 + arow) * 144u + bcol;
                    ldsm4t(&bf[0][0], brow);        // nb0,nb1 (klo/khi each)
                    ldsm4t(&bf[2][0], brow + 32u);  // nb2,nb3 (cols +16)
                    #pragma unroll
                    for (int mb = 0; mb < 2; ++mb) {
                        uint32_t af[4];
                        ldsm4(af, sa_base + (uint32_t)t * A_TERMB
                                 + (uint32_t)(mrow + mb * 16 + arow + kw) * 144u
                                 + ahalf + (uint32_t)k * 32u);
                        #pragma unroll
                        for (int nb = 0; nb < 4; ++nb)
                            mma16816(acc[mb][nb], af, bf[nb]);
                    }
                }
            }
        }
    }

    // ---- epilogue: scale + bias + PReLU + act fake-quant -> g_h ------------
    #pragma unroll
    for (int mb = 0; mb < 2; ++mb)
        #pragma unroll
        for (int nb = 0; nb < 4; ++nb)
            #pragma unroll
            for (int rg = 0; rg < 4; ++rg) {
                int j  = mrow + mb * 16 + (lane >> 2) + (rg >> 1) * 8;
                int oc = ncol + nb * 8 + ((lane & 3) << 1) + (rg & 1);
                float v  = acc[mb][nb][rg] * s_prm[oc] + s_prm[64 + oc];
                float pv = (v >= 0.f) ? v : s_prm[128 + oc] * v;
                float ss = s_prm[192 + oc];
                float q  = rintf(pv / ss);
                q = fminf(fmaxf(q, -64.f), 63.f);
                g_h[(((n * 64 + oc) * 256 + y) << 8) + x0 + j] = q * ss;
            }
}

// ---------------- conv2: fp32 FFMA2 (proven R4 kernel, unchanged) -----------
#define TH2   8
#define T2W   128
#define CC2   4
#define P2R   10
#define P2CW  130
#define P2W   131

__global__ __launch_bounds__(128, 6)
void conv2_kernel(const float* __restrict__ b2,
                  const float* __restrict__ alpha2,
                  const float* __restrict__ sa2,
                  float* __restrict__ out)
{
    __shared__ __align__(16) float s_in[CC2 * P2R * P2W];
    __shared__ __align__(16) float s_w2[CC2 * 9 * 4];

    const int tid = threadIdx.x;
    const int bid = blockIdx.x;
    const int tx  = bid & 1;
    const int ty  = (bid >> 1) & 31;
    const int n   = bid >> 6;
    const int x0  = tx * T2W;
    const int y0  = ty * TH2;

    const int r    = tid & 7;
    const int g    = (tid >> 3) & 3;
    const int warp = tid >> 5;
    const int cb   = warp * 32 + g * 8;

    unsigned long long acc[2][8];
    #pragma unroll
    for (int i = 0; i < 2; ++i)
        #pragma unroll
        for (int j = 0; j < 8; ++j) acc[i][j] = 0ULL;

    for (int c0 = 0; c0 < CIN; c0 += CC2) {
        __syncthreads();
        for (int idx = tid; idx < CC2 * P2R * P2CW; idx += 128) {
            int c   = idx / (P2R * P2CW);
            int rem = idx - c * (P2R * P2CW);
            int row = rem / P2CW;
            int col = rem - row * P2CW;
            int gy  = y0 + row - 1;
            int gx  = x0 + col - 1;
            float v = 0.f;
            if ((unsigned)gy < 256u && (unsigned)gx < 256u)
                v = g_h[(((n * CIN + c0 + c) * 256 + gy) << 8) + gx];
            s_in[(c * P2R + row) * P2W + col] = v;
        }
        for (int idx = tid; idx < CC2 * 9 * 4; idx += 128)
            s_w2[idx] = g_w2q[c0 * 9 * 4 + idx];
        __syncthreads();

        #pragma unroll 1
        for (int c = 0; c < CC2; ++c) {
            #pragma unroll
            for (int kh = 0; kh < 3; ++kh) {
                const float* rowp = &s_in[(c * P2R + r + kh) * P2W + cb];
                unsigned long long v2[10];
                #pragma unroll
                for (int i = 0; i < 10; ++i) {
                    unsigned int u = __float_as_uint(rowp[i]);
                    asm("mov.b64 %0, {%1, %1};" : "=l"(v2[i]) : "r"(u));
                }
                #pragma unroll
                for (int kw = 0; kw < 3; ++kw) {
                    const unsigned long long* wp = (const unsigned long long*)
                        &s_w2[(c * 9 + kh * 3 + kw) << 2];
                    unsigned long long w0 = wp[0];
                    unsigned long long w1 = wp[1];
                    #pragma unroll
                    for (int px = 0; px < 8; ++px) {
                        asm("fma.rn.f32x2 %0, %1, %2, %0;"
                            : "+l"(acc[0][px]) : "l"(w0), "l"(v2[px + kw]));
                        asm("fma.rn.f32x2 %0, %1, %2, %0;"
                            : "+l"(acc[1][px]) : "l"(w1), "l"(v2[px + kw]));
                    }
                }
            }
        }
    }

    const int gy = y0 + r;
    const int gx = x0 + cb;
    #pragma unroll
    for (int cp = 0; cp < 2; ++cp) {
        float lo[8], hi[8];
        #pragma unroll
        for (int px = 0; px < 8; ++px) {
            unsigned int a, b;
            asm("mov.b64 {%0, %1}, %2;" : "=r"(a), "=r"(b) : "l"(acc[cp][px]));
            lo[px] = __uint_as_float(a);
            hi[px] = __uint_as_float(b);
        }
        #pragma unroll
        for (int half = 0; half < 2; ++half) {
            int oc = (cp << 1) + half;
            if (oc >= 3) continue;
            const float* v = half ? hi : lo;
            float bb = b2[oc], aa = alpha2[oc], ss = sa2[oc];
            float o[8];
            #pragma unroll
            for (int i = 0; i < 8; ++i) {
                float yv = v[i] + bb;
                float pv = (yv >= 0.f) ? yv : aa * yv;
                float q = rintf(pv / ss);
                q = fminf(fmaxf(q, -64.f), 63.f);
                o[i] = q * ss;
            }
            float4* p4 = reinterpret_cast<float4*>(
                &out[(((n * 3 + oc) * 256 + gy) << 8) + gx]);
            p4[0] = make_float4(o[0], o[1], o[2], o[3]);
            p4[1] = make_float4(o[4], o[5], o[6], o[7]);
        }
    }
}

// ---------------------------------------------------------------------------
extern "C" void kernel_launch(void* const* d_in, const int* in_sizes, int n_in,
                              void* d_out, int out_size)
{
    const float* x      = (const float*)d_in[0];
    const float* w1     = (const float*)d_in[1];
    const float* b1     = (const float*)d_in[2];
    const float* w2     = (const float*)d_in[3];
    const float* b2     = (const float*)d_in[4];
    const float* alpha1 = (const float*)d_in[5];
    const float* alpha2 = (const float*)d_in[6];
    const float* sw1    = (const float*)d_in[7];
    const float* sw2    = (const float*)d_in[8];
    const float* sa1    = (const float*)d_in[9];
    const float* sa2    = (const float*)d_in[10];
    float* out = (float*)d_out;

    cudaFuncSetAttribute(conv1_mma_kernel,
                         cudaFuncAttributeMaxDynamicSharedMemorySize, SMEM1);

    prequant_kernel<<<(9 * 64 * 64 + 64 * 9 * 4 + 255) / 256, 256>>>(w1, sw1, w2, sw2);
    conv1_mma_kernel<<<NB * 256 * 2, 256, SMEM1>>>(x, sw1, b1, alpha1, sa1);
    conv2_kernel<<<NB * 32 * 2, 128>>>(b2, alpha2, sa2, out);
    tick_kernel<<<1, 32>>>();   // period 3 -> 4: ncu slot 6 lands on conv1
}

// round 14
// speedup vs baseline: 1.1760x; 1.1760x over previous
#include <cuda_runtime.h>
#include <cuda_fp16.h>
#include <cstdint>

// ---------------------------------------------------------------------------
// R14: conv1 = R11 exactly (best measured: 507us; x2.trans B loads, occ 3,
//      cp.async ping-pong W). Launch order prequant,tick,tick,conv1,conv2
//      so ncu's captured index (==3 mod period) lands on conv1.
//      conv2 = proven R4 fp32 FFMA2 kernel.
// ---------------------------------------------------------------------------

#define IMG   256
#define NB    8
#define CIN   64

__device__ float  g_h[NB * CIN * IMG * IMG];
__device__ __half g_w1h[9 * 64 * 64];          // [tap][c][oc] linear
__device__ float  g_w2q[CIN * 9 * 4];

__device__ __forceinline__ uint32_t smem_u32(const void* p) {
    uint32_t a;
    asm("{ .reg .u64 t; cvta.to.shared.u64 t, %1; cvt.u32.u64 %0, t; }"
        : "=r"(a) : "l"(p));
    return a;
}
__device__ __forceinline__ void ldsm4(uint32_t* r, uint32_t addr) {
    asm volatile("ldmatrix.sync.aligned.m8n8.x4.shared.b16 {%0,%1,%2,%3}, [%4];"
        : "=r"(r[0]), "=r"(r[1]), "=r"(r[2]), "=r"(r[3]) : "r"(addr));
}
__device__ __forceinline__ void ldsm2t(uint32_t& r0, uint32_t& r1, uint32_t addr) {
    asm volatile("ldmatrix.sync.aligned.m8n8.x2.trans.shared.b16 {%0,%1}, [%2];"
        : "=r"(r0), "=r"(r1) : "r"(addr));
}
__device__ __forceinline__ void mma16816(float* c, const uint32_t* a, const uint32_t* b) {
    asm volatile("mma.sync.aligned.m16n8k16.row.col.f32.f16.f16.f32 "
        "{%0,%1,%2,%3}, {%4,%5,%6,%7}, {%8,%9}, {%0,%1,%2,%3};"
        : "+f"(c[0]), "+f"(c[1]), "+f"(c[2]), "+f"(c[3])
        : "r"(a[0]), "r"(a[1]), "r"(a[2]), "r"(a[3]), "r"(b[0]), "r"(b[1]));
}
__device__ __forceinline__ void cp16(uint32_t dst, const void* src) {
    asm volatile("cp.async.cg.shared.global [%0], [%1], 16;"
        :: "r"(dst), "l"(src));
}
#define CP_COMMIT() asm volatile("cp.async.commit_group;" ::: "memory")
#define CP_WAIT0()  asm volatile("cp.async.wait_group 0;"  ::: "memory")

// dynamic smem layout:
#define A_TERMB 18720u                 // 130 rows x 144B per split term
#define W_OFF   37440u
#define W_BUF   9216u
#define P_OFF   (W_OFF + 2u * W_BUF)   // 55872
#define SMEM1   (P_OFF + 1024u)        // 56896 -> occ 3 (170.7KB)

// ---------------- prequant (one-shot) ---------------------------------------
__global__ void prequant_kernel(const float* __restrict__ w1,
                                const float* __restrict__ sw1,
                                const float* __restrict__ w2,
                                const float* __restrict__ sw2)
{
    int idx = blockIdx.x * 256 + threadIdx.x;
    if (idx < 9 * 64 * 64) {
        int oc  = idx & 63;
        int c   = (idx >> 6) & 63;
        int tap = idx >> 12;
        float w = w1[(oc * 64 + c) * 9 + tap];
        float s = sw1[oc];
        float q = rintf(w / s);
        q = fminf(fmaxf(q, -64.f), 63.f);
        g_w1h[idx] = __float2half_rn(q);        // exact 7-bit integer
    } else if (idx < 9 * 64 * 64 + 64 * 9 * 4) {
        int j  = idx - 9 * 64 * 64;
        int oc = j & 3;
        int k  = j >> 2;
        int c  = k / 9;
        int kk = k - c * 9;
        float v = 0.f;
        if (oc < 3) {
            float w = w2[(oc * CIN + c) * 9 + kk];
            float s = sw2[oc];
            float q = rintf(w / s);
            q = fminf(fmaxf(q, -64.f), 63.f);
            v = q * s;
        }
        g_w2q[j] = v;
    }
}

// tiny no-op launches: position conv1 at captured index 3 (mod 5)
__global__ void tick_kernel() {}

// ---------------- conv1: HMMA, occ 3 (R11 code, best measured) ---------------
// CTA = 128-px row strip (n, y, x0), 64 oc. 256 thr = 8 warps.
// Warp tile: 32 px (mrow=(w&3)*32) x 32 oc (ncol=(w>>2)*32).
__global__ __launch_bounds__(256, 3)
void conv1_mma_kernel(const float* __restrict__ x,
                      const float* __restrict__ sw1,
                      const float* __restrict__ b1,
                      const float* __restrict__ alpha1,
                      const float* __restrict__ sa1)
{
    extern __shared__ unsigned char sm[];
    __half* s_a   = (__half*)sm;
    float*  s_prm = (float*)(sm + P_OFF);
    const uint32_t sa_base = smem_u32(sm);
    const uint32_t sw_base = sa_base + W_OFF;

    const int tid  = threadIdx.x;
    const int lane = tid & 31;
    const int warp = tid >> 5;
    const int mrow = (warp & 3) * 32;
    const int ncol = (warp >> 2) * 32;

    const int bid = blockIdx.x;          // 8n * 256y * 2xt = 4096
    const int x0  = (bid & 1) * 128;
    const int y   = (bid >> 1) & 255;
    const int n   = bid >> 9;

    // ---- prefetch W tap 0 via cp.async (overlaps params + A build) ----
    {
        const char* src = (const char*)g_w1h;
        uint32_t dst = sw_base + (uint32_t)(tid >> 3) * 144u
                     + (uint32_t)(tid & 7) * 16u;
        cp16(dst, src + tid * 16);
        cp16(dst + (256 >> 3) * 144u, src + (tid + 256) * 16);
        CP_COMMIT();
    }

    if (tid < 256) {
        int a = tid >> 6, oc = tid & 63;
        const float* src = (a == 0) ? sw1 : (a == 1) ? b1 : (a == 2) ? alpha1 : sa1;
        s_prm[a * 64 + oc] = src[oc];
    }

    float acc[2][4][4];
    #pragma unroll
    for (int i = 0; i < 2; ++i)
        #pragma unroll
        for (int j = 0; j < 4; ++j)
            #pragma unroll
            for (int k = 0; k < 4; ++k) acc[i][j][k] = 0.f;

    const uint32_t arow  = lane & 15;
    const uint32_t ahalf = (lane >> 4) * 16;

    for (int s = 0; s < 3; ++s) {
        const int gy = y + s - 1;
        const bool row_ok = (unsigned)gy < 256u;
        if (s) __syncthreads();            // prior tap's A reads done
        // ---- build exact fp16 2-term split strip (144B rows) ----
        for (int idx = tid; idx < 64 * 130; idx += 256) {
            int c = idx / 130;
            int j = idx - c * 130;
            int gx = x0 - 1 + j;
            float v = 0.f;
            if (row_ok && (unsigned)gx < 256u)
                v = x[(((n * 64 + c) * 256 + gy) << 8) + gx];
            __half hi = __float2half_rn(v);
            __half lo = __float2half_rn(v - __half2float(hi));
            s_a[j * 72 + c]        = hi;
            s_a[9360 + j * 72 + c] = lo;   // 9360 halves = A_TERMB bytes
        }

        for (int kw = 0; kw < 3; ++kw) {
            const int tap = s * 3 + kw;
            CP_WAIT0();                    // W[tap] landed in buf[tap&1]
            __syncthreads();               // W (+A on kw==0) visible to all
            if (tap < 8) {                 // prefetch next tap into other buf
                const char* src = (const char*)g_w1h + (tap + 1) * 8192;
                uint32_t dst = sw_base + ((uint32_t)(tap + 1) & 1u) * W_BUF
                             + (uint32_t)(tid >> 3) * 144u
                             + (uint32_t)(tid & 7) * 16u;
                cp16(dst, src + tid * 16);
                cp16(dst + (256 >> 3) * 144u, src + (tid + 256) * 16);
                CP_COMMIT();
            }
            const uint32_t swb = sw_base + ((uint32_t)tap & 1u) * W_BUF;

            // per-accumulator order: t0:k0..k3, t1:k0..k3
            #pragma unroll
            for (int t = 0; t < 2; ++t) {
                #pragma unroll
                for (int k = 0; k < 4; ++k) {
                    uint32_t bf[4][2];
                    #pragma unroll
                    for (int nb = 0; nb < 4; ++nb)
                        ldsm2t(bf[nb][0], bf[nb][1],
                               swb + (uint32_t)(k * 16 + arow) * 144u
                                   + (uint32_t)(ncol + nb * 8) * 2u);
                    #pragma unroll
                    for (int mb = 0; mb < 2; ++mb) {
                        uint32_t af[4];
                        ldsm4(af, sa_base + (uint32_t)t * A_TERMB
                                 + (uint32_t)(mrow + mb * 16 + arow + kw) * 144u
                                 + ahalf + (uint32_t)k * 32u);
                        #pragma unroll
                        for (int nb = 0; nb < 4; ++nb)
                            mma16816(acc[mb][nb], af, bf[nb]);
                    }
                }
            }
        }
    }

    // ---- epilogue: scale + bias + PReLU + act fake-quant -> g_h ------------
    #pragma unroll
    for (int mb = 0; mb < 2; ++mb)
        #pragma unroll
        for (int nb = 0; nb < 4; ++nb)
            #pragma unroll
            for (int rg = 0; rg < 4; ++rg) {
                int j  = mrow + mb * 16 + (lane >> 2) + (rg >> 1) * 8;
                int oc = ncol + nb * 8 + ((lane & 3) << 1) + (rg & 1);
                float v  = acc[mb][nb][rg] * s_prm[oc] + s_prm[64 + oc];
                float pv = (v >= 0.f) ? v : s_prm[128 + oc] * v;
                float ss = s_prm[192 + oc];
                float q  = rintf(pv / ss);
                q = fminf(fmaxf(q, -64.f), 63.f);
                g_h[(((n * 64 + oc) * 256 + y) << 8) + x0 + j] = q * ss;
            }
}

// ---------------- conv2: fp32 FFMA2 (proven R4 kernel, unchanged) -----------
#define TH2   8
#define T2W   128
#define CC2   4
#define P2R   10
#define P2CW  130
#define P2W   131

__global__ __launch_bounds__(128, 6)
void conv2_kernel(const float* __restrict__ b2,
                  const float* __restrict__ alpha2,
                  const float* __restrict__ sa2,
                  float* __restrict__ out)
{
    __shared__ __align__(16) float s_in[CC2 * P2R * P2W];
    __shared__ __align__(16) float s_w2[CC2 * 9 * 4];

    const int tid = threadIdx.x;
    const int bid = blockIdx.x;
    const int tx  = bid & 1;
    const int ty  = (bid >> 1) & 31;
    const int n   = bid >> 6;
    const int x0  = tx * T2W;
    const int y0  = ty * TH2;

    const int r    = tid & 7;
    const int g    = (tid >> 3) & 3;
    const int warp = tid >> 5;
    const int cb   = warp * 32 + g * 8;

    unsigned long long acc[2][8];
    #pragma unroll
    for (int i = 0; i < 2; ++i)
        #pragma unroll
        for (int j = 0; j < 8; ++j) acc[i][j] = 0ULL;

    for (int c0 = 0; c0 < CIN; c0 += CC2) {
        __syncthreads();
        for (int idx = tid; idx < CC2 * P2R * P2CW; idx += 128) {
            int c   = idx / (P2R * P2CW);
            int rem = idx - c * (P2R * P2CW);
            int row = rem / P2CW;
            int col = rem - row * P2CW;
            int gy  = y0 + row - 1;
            int gx  = x0 + col - 1;
            float v = 0.f;
            if ((unsigned)gy < 256u && (unsigned)gx < 256u)
                v = g_h[(((n * CIN + c0 + c) * 256 + gy) << 8) + gx];
            s_in[(c * P2R + row) * P2W + col] = v;
        }
        for (int idx = tid; idx < CC2 * 9 * 4; idx += 128)
            s_w2[idx] = g_w2q[c0 * 9 * 4 + idx];
        __syncthreads();

        #pragma unroll 1
        for (int c = 0; c < CC2; ++c) {
            #pragma unroll
            for (int kh = 0; kh < 3; ++kh) {
                const float* rowp = &s_in[(c * P2R + r + kh) * P2W + cb];
                unsigned long long v2[10];
                #pragma unroll
                for (int i = 0; i < 10; ++i) {
                    unsigned int u = __float_as_uint(rowp[i]);
                    asm("mov.b64 %0, {%1, %1};" : "=l"(v2[i]) : "r"(u));
                }
                #pragma unroll
                for (int kw = 0; kw < 3; ++kw) {
                    const unsigned long long* wp = (const unsigned long long*)
                        &s_w2[(c * 9 + kh * 3 + kw) << 2];
                    unsigned long long w0 = wp[0];
                    unsigned long long w1 = wp[1];
                    #pragma unroll
                    for (int px = 0; px < 8; ++px) {
                        asm("fma.rn.f32x2 %0, %1, %2, %0;"
                            : "+l"(acc[0][px]) : "l"(w0), "l"(v2[px + kw]));
                        asm("fma.rn.f32x2 %0, %1, %2, %0;"
                            : "+l"(acc[1][px]) : "l"(w1), "l"(v2[px + kw]));
                    }
                }
            }
        }
    }

    const int gy = y0 + r;
    const int gx = x0 + cb;
    #pragma unroll
    for (int cp = 0; cp < 2; ++cp) {
        float lo[8], hi[8];
        #pragma unroll
        for (int px = 0; px < 8; ++px) {
            unsigned int a, b;
            asm("mov.b64 {%0, %1}, %2;" : "=r"(a), "=r"(b) : "l"(acc[cp][px]));
            lo[px] = __uint_as_float(a);
            hi[px] = __uint_as_float(b);
        }
        #pragma unroll
        for (int half = 0; half < 2; ++half) {
            int oc = (cp << 1) + half;
            if (oc >= 3) continue;
            const float* v = half ? hi : lo;
            float bb = b2[oc], aa = alpha2[oc], ss = sa2[oc];
            float o[8];
            #pragma unroll
            for (int i = 0; i < 8; ++i) {
                float yv = v[i] + bb;
                float pv = (yv >= 0.f) ? yv : aa * yv;
                float q = rintf(pv / ss);
                q = fminf(fmaxf(q, -64.f), 63.f);
                o[i] = q * ss;
            }
            float4* p4 = reinterpret_cast<float4*>(
                &out[(((n * 3 + oc) * 256 + gy) << 8) + gx]);
            p4[0] = make_float4(o[0], o[1], o[2], o[3]);
            p4[1] = make_float4(o[4], o[5], o[6], o[7]);
        }
    }
}

// ---------------------------------------------------------------------------
extern "C" void kernel_launch(void* const* d_in, const int* in_sizes, int n_in,
                              void* d_out, int out_size)
{
    const float* x      = (const float*)d_in[0];
    const float* w1     = (const float*)d_in[1];
    const float* b1     = (const float*)d_in[2];
    const float* w2     = (const float*)d_in[3];
    const float* b2     = (const float*)d_in[4];
    const float* alpha1 = (const float*)d_in[5];
    const float* alpha2 = (const float*)d_in[6];
    const float* sw1    = (const float*)d_in[7];
    const float* sw2    = (const float*)d_in[8];
    const float* sa1    = (const float*)d_in[9];
    const float* sa2    = (const float*)d_in[10];
    float* out = (float*)d_out;

    cudaFuncSetAttribute(conv1_mma_kernel,
                         cudaFuncAttributeMaxDynamicSharedMemorySize, SMEM1);

    // captured ncu index == 3 (mod period): place conv1 at index 3.
    prequant_kernel<<<(9 * 64 * 64 + 64 * 9 * 4 + 255) / 256, 256>>>(w1, sw1, w2, sw2);
    tick_kernel<<<1, 32>>>();
    tick_kernel<<<1, 32>>>();
    conv1_mma_kernel<<<NB * 256 * 2, 256, SMEM1>>>(x, sw1, b1, alpha1, sa1);
    conv2_kernel<<<NB * 32 * 2, 128>>>(b2, alpha2, sa2, out);
}

// round 15
// speedup vs baseline: 1.4000x; 1.1905x over previous
#include <cuda_runtime.h>
#include <cuda_fp16.h>
#include <cstdint>

// ---------------------------------------------------------------------------
// R15: R14 (= R11 MMA core, best 507us) + A-build v2: div/mod-free indexing,
//      conflict-free u32 STS, 32B-sector LDG. Stored bytes identical =>
//      fragments and rel_err byte-identical. conv2 = proven R4 kernel.
// ---------------------------------------------------------------------------

#define IMG   256
#define NB    8
#define CIN   64

__device__ float  g_h[NB * CIN * IMG * IMG];
__device__ __half g_w1h[9 * 64 * 64];          // [tap][c][oc] linear
__device__ float  g_w2q[CIN * 9 * 4];

__device__ __forceinline__ uint32_t smem_u32(const void* p) {
    uint32_t a;
    asm("{ .reg .u64 t; cvta.to.shared.u64 t, %1; cvt.u32.u64 %0, t; }"
        : "=r"(a) : "l"(p));
    return a;
}
__device__ __forceinline__ void ldsm4(uint32_t* r, uint32_t addr) {
    asm volatile("ldmatrix.sync.aligned.m8n8.x4.shared.b16 {%0,%1,%2,%3}, [%4];"
        : "=r"(r[0]), "=r"(r[1]), "=r"(r[2]), "=r"(r[3]) : "r"(addr));
}
__device__ __forceinline__ void ldsm2t(uint32_t& r0, uint32_t& r1, uint32_t addr) {
    asm volatile("ldmatrix.sync.aligned.m8n8.x2.trans.shared.b16 {%0,%1}, [%2];"
        : "=r"(r0), "=r"(r1) : "r"(addr));
}
__device__ __forceinline__ void mma16816(float* c, const uint32_t* a, const uint32_t* b) {
    asm volatile("mma.sync.aligned.m16n8k16.row.col.f32.f16.f16.f32 "
        "{%0,%1,%2,%3}, {%4,%5,%6,%7}, {%8,%9}, {%0,%1,%2,%3};"
        : "+f"(c[0]), "+f"(c[1]), "+f"(c[2]), "+f"(c[3])
        : "r"(a[0]), "r"(a[1]), "r"(a[2]), "r"(a[3]), "r"(b[0]), "r"(b[1]));
}
__device__ __forceinline__ void cp16(uint32_t dst, const void* src) {
    asm volatile("cp.async.cg.shared.global [%0], [%1], 16;"
        :: "r"(dst), "l"(src));
}
#define CP_COMMIT() asm volatile("cp.async.commit_group;" ::: "memory")
#define CP_WAIT0()  asm volatile("cp.async.wait_group 0;"  ::: "memory")

// dynamic smem layout:
#define A_TERMB 18720u                 // 130 rows x 144B per split term
#define W_OFF   37440u
#define W_BUF   9216u
#define P_OFF   (W_OFF + 2u * W_BUF)   // 55872
#define SMEM1   (P_OFF + 1024u)        // 56896 -> occ 3 (170.7KB)

// ---------------- prequant (one-shot) ---------------------------------------
__global__ void prequant_kernel(const float* __restrict__ w1,
                                const float* __restrict__ sw1,
                                const float* __restrict__ w2,
                                const float* __restrict__ sw2)
{
    int idx = blockIdx.x * 256 + threadIdx.x;
    if (idx < 9 * 64 * 64) {
        int oc  = idx & 63;
        int c   = (idx >> 6) & 63;
        int tap = idx >> 12;
        float w = w1[(oc * 64 + c) * 9 + tap];
        float s = sw1[oc];
        float q = rintf(w / s);
        q = fminf(fmaxf(q, -64.f), 63.f);
        g_w1h[idx] = __float2half_rn(q);        // exact 7-bit integer
    } else if (idx < 9 * 64 * 64 + 64 * 9 * 4) {
        int j  = idx - 9 * 64 * 64;
        int oc = j & 3;
        int k  = j >> 2;
        int c  = k / 9;
        int kk = k - c * 9;
        float v = 0.f;
        if (oc < 3) {
            float w = w2[(oc * CIN + c) * 9 + kk];
            float s = sw2[oc];
            float q = rintf(w / s);
            q = fminf(fmaxf(q, -64.f), 63.f);
            v = q * s;
        }
        g_w2q[j] = v;
    }
}

// tiny no-op launches: position conv1 at captured index 3 (mod 5)
__global__ void tick_kernel() {}

// ---------------- conv1: HMMA, occ 3, fast A-build ---------------------------
// CTA = 128-px row strip (n, y, x0), 64 oc. 256 thr = 8 warps.
// Warp tile: 32 px (mrow=(w&3)*32) x 32 oc (ncol=(w>>2)*32).
__global__ __launch_bounds__(256, 3)
void conv1_mma_kernel(const float* __restrict__ x,
                      const float* __restrict__ sw1,
                      const float* __restrict__ b1,
                      const float* __restrict__ alpha1,
                      const float* __restrict__ sa1)
{
    extern __shared__ unsigned char sm[];
    float* s_prm = (float*)(sm + P_OFF);
    const uint32_t sa_base = smem_u32(sm);
    const uint32_t sw_base = sa_base + W_OFF;

    const int tid  = threadIdx.x;
    const int lane = tid & 31;
    const int warp = tid >> 5;
    const int mrow = (warp & 3) * 32;
    const int ncol = (warp >> 2) * 32;

    const int bid = blockIdx.x;          // 8n * 256y * 2xt = 4096
    const int x0  = (bid & 1) * 128;
    const int y   = (bid >> 1) & 255;
    const int n   = bid >> 9;

    // A-build mapping (div/mod-free, conflict-free stores)
    const int cp  = tid >> 3;            // channel pair 0..31  (c = 2cp, 2cp+1)
    const int jlo = tid & 7;             // j = jlo + 8*iter

    // ---- prefetch W tap 0 via cp.async (overlaps params + A build) ----
    {
        const char* src = (const char*)g_w1h;
        uint32_t dst = sw_base + (uint32_t)(tid >> 3) * 144u
                     + (uint32_t)(tid & 7) * 16u;
        cp16(dst, src + tid * 16);
        cp16(dst + (256 >> 3) * 144u, src + (tid + 256) * 16);
        CP_COMMIT();
    }

    if (tid < 256) {
        int a = tid >> 6, oc = tid & 63;
        const float* src = (a == 0) ? sw1 : (a == 1) ? b1 : (a == 2) ? alpha1 : sa1;
        s_prm[a * 64 + oc] = src[oc];
    }

    float acc[2][4][4];
    #pragma unroll
    for (int i = 0; i < 2; ++i)
        #pragma unroll
        for (int j = 0; j < 4; ++j)
            #pragma unroll
            for (int k = 0; k < 4; ++k) acc[i][j][k] = 0.f;

    const uint32_t arow  = lane & 15;
    const uint32_t ahalf = (lane >> 4) * 16;

    for (int s = 0; s < 3; ++s) {
        const int gy = y + s - 1;
        const bool row_ok = (unsigned)gy < 256u;
        if (s) __syncthreads();            // prior tap's A reads done
        // ---- A-build v2: exact fp16 2-term split, u32 stores ----
        {
            // base pointers for the two channels of this thread's pair
            const float* xc0 = x + (((n * 64 + 2 * cp) * 256 + gy) << 8) + x0 - 1;
            const float* xc1 = xc0 + 65536;          // next channel
            #pragma unroll
            for (int it = 0; it < 17; ++it) {
                int j = jlo + (it << 3);
                if (j < 130) {
                    int gx = x0 - 1 + j;
                    float v0 = 0.f, v1 = 0.f;
                    if (row_ok && (unsigned)gx < 256u) { v0 = xc0[j]; v1 = xc1[j]; }
                    __half h0 = __float2half_rn(v0);
                    __half l0 = __float2half_rn(v0 - __half2float(h0));
                    __half h1 = __float2half_rn(v1);
                    __half l1 = __float2half_rn(v1 - __half2float(h1));
                    uint32_t hh = ((uint32_t)__half_as_ushort(h1) << 16)
                                |  (uint32_t)__half_as_ushort(h0);
                    uint32_t ll = ((uint32_t)__half_as_ushort(l1) << 16)
                                |  (uint32_t)__half_as_ushort(l0);
                    uint32_t off = (uint32_t)j * 144u + (uint32_t)cp * 4u;
                    *(uint32_t*)(sm + off)           = hh;
                    *(uint32_t*)(sm + A_TERMB + off) = ll;
                }
            }
        }

        for (int kw = 0; kw < 3; ++kw) {
            const int tap = s * 3 + kw;
            CP_WAIT0();                    // W[tap] landed in buf[tap&1]
            __syncthreads();               // W (+A on kw==0) visible to all
            if (tap < 8) {                 // prefetch next tap into other buf
                const char* src = (const char*)g_w1h + (tap + 1) * 8192;
                uint32_t dst = sw_base + ((uint32_t)(tap + 1) & 1u) * W_BUF
                             + (uint32_t)(tid >> 3) * 144u
                             + (uint32_t)(tid & 7) * 16u;
                cp16(dst, src + tid * 16);
                cp16(dst + (256 >> 3) * 144u, src + (tid + 256) * 16);
                CP_COMMIT();
            }
            const uint32_t swb = sw_base + ((uint32_t)tap & 1u) * W_BUF;

            // per-accumulator order: t0:k0..k3, t1:k0..k3  (== R11 exactly)
            #pragma unroll
            for (int t = 0; t < 2; ++t) {
                #pragma unroll
                for (int k = 0; k < 4; ++k) {
                    uint32_t bf[4][2];
                    #pragma unroll
                    for (int nb = 0; nb < 4; ++nb)
                        ldsm2t(bf[nb][0], bf[nb][1],
                               swb + (uint32_t)(k * 16 + arow) * 144u
                                   + (uint32_t)(ncol + nb * 8) * 2u);
                    #pragma unroll
                    for (int mb = 0; mb < 2; ++mb) {
                        uint32_t af[4];
                        ldsm4(af, sa_base + (uint32_t)t * A_TERMB
                                 + (uint32_t)(mrow + mb * 16 + arow + kw) * 144u
                                 + ahalf + (uint32_t)k * 32u);
                        #pragma unroll
                        for (int nb = 0; nb < 4; ++nb)
                            mma16816(acc[mb][nb], af, bf[nb]);
                    }
                }
            }
        }
    }

    // ---- epilogue: scale + bias + PReLU + act fake-quant -> g_h ------------
    #pragma unroll
    for (int mb = 0; mb < 2; ++mb)
        #pragma unroll
        for (int nb = 0; nb < 4; ++nb)
            #pragma unroll
            for (int rg = 0; rg < 4; ++rg) {
                int j  = mrow + mb * 16 + (lane >> 2) + (rg >> 1) * 8;
                int oc = ncol + nb * 8 + ((lane & 3) << 1) + (rg & 1);
                float v  = acc[mb][nb][rg] * s_prm[oc] + s_prm[64 + oc];
                float pv = (v >= 0.f) ? v : s_prm[128 + oc] * v;
                float ss = s_prm[192 + oc];
                float q  = rintf(pv / ss);
                q = fminf(fmaxf(q, -64.f), 63.f);
                g_h[(((n * 64 + oc) * 256 + y) << 8) + x0 + j] = q * ss;
            }
}

// ---------------- conv2: fp32 FFMA2 (proven R4 kernel, unchanged) -----------
#define TH2   8
#define T2W   128
#define CC2   4
#define P2R   10
#define P2CW  130
#define P2W   131

__global__ __launch_bounds__(128, 6)
void conv2_kernel(const float* __restrict__ b2,
                  const float* __restrict__ alpha2,
                  const float* __restrict__ sa2,
                  float* __restrict__ out)
{
    __shared__ __align__(16) float s_in[CC2 * P2R * P2W];
    __shared__ __align__(16) float s_w2[CC2 * 9 * 4];

    const int tid = threadIdx.x;
    const int bid = blockIdx.x;
    const int tx  = bid & 1;
    const int ty  = (bid >> 1) & 31;
    const int n   = bid >> 6;
    const int x0  = tx * T2W;
    const int y0  = ty * TH2;

    const int r    = tid & 7;
    const int g    = (tid >> 3) & 3;
    const int warp = tid >> 5;
    const int cb   = warp * 32 + g * 8;

    unsigned long long acc[2][8];
    #pragma unroll
    for (int i = 0; i < 2; ++i)
        #pragma unroll
        for (int j = 0; j < 8; ++j) acc[i][j] = 0ULL;

    for (int c0 = 0; c0 < CIN; c0 += CC2) {
        __syncthreads();
        for (int idx = tid; idx < CC2 * P2R * P2CW; idx += 128) {
            int c   = idx / (P2R * P2CW);
            int rem = idx - c * (P2R * P2CW);
            int row = rem / P2CW;
            int col = rem - row * P2CW;
            int gy  = y0 + row - 1;
            int gx  = x0 + col - 1;
            float v = 0.f;
            if ((unsigned)gy < 256u && (unsigned)gx < 256u)
                v = g_h[(((n * CIN + c0 + c) * 256 + gy) << 8) + gx];
            s_in[(c * P2R + row) * P2W + col] = v;
        }
        for (int idx = tid; idx < CC2 * 9 * 4; idx += 128)
            s_w2[idx] = g_w2q[c0 * 9 * 4 + idx];
        __syncthreads();

        #pragma unroll 1
        for (int c = 0; c < CC2; ++c) {
            #pragma unroll
            for (int kh = 0; kh < 3; ++kh) {
                const float* rowp = &s_in[(c * P2R + r + kh) * P2W + cb];
                unsigned long long v2[10];
                #pragma unroll
                for (int i = 0; i < 10; ++i) {
                    unsigned int u = __float_as_uint(rowp[i]);
                    asm("mov.b64 %0, {%1, %1};" : "=l"(v2[i]) : "r"(u));
                }
                #pragma unroll
                for (int kw = 0; kw < 3; ++kw) {
                    const unsigned long long* wp = (const unsigned long long*)
                        &s_w2[(c * 9 + kh * 3 + kw) << 2];
                    unsigned long long w0 = wp[0];
                    unsigned long long w1 = wp[1];
                    #pragma unroll
                    for (int px = 0; px < 8; ++px) {
                        asm("fma.rn.f32x2 %0, %1, %2, %0;"
                            : "+l"(acc[0][px]) : "l"(w0), "l"(v2[px + kw]));
                        asm("fma.rn.f32x2 %0, %1, %2, %0;"
                            : "+l"(acc[1][px]) : "l"(w1), "l"(v2[px + kw]));
                    }
                }
            }
        }
    }

    const int gy = y0 + r;
    const int gx = x0 + cb;
    #pragma unroll
    for (int cp = 0; cp < 2; ++cp) {
        float lo[8], hi[8];
        #pragma unroll
        for (int px = 0; px < 8; ++px) {
            unsigned int a, b;
            asm("mov.b64 {%0, %1}, %2;" : "=r"(a), "=r"(b) : "l"(acc[cp][px]));
            lo[px] = __uint_as_float(a);
            hi[px] = __uint_as_float(b);
        }
        #pragma unroll
        for (int half = 0; half < 2; ++half) {
            int oc = (cp << 1) + half;
            if (oc >= 3) continue;
            const float* v = half ? hi : lo;
            float bb = b2[oc], aa = alpha2[oc], ss = sa2[oc];
            float o[8];
            #pragma unroll
            for (int i = 0; i < 8; ++i) {
                float yv = v[i] + bb;
                float pv = (yv >= 0.f) ? yv : aa * yv;
                float q = rintf(pv / ss);
                q = fminf(fmaxf(q, -64.f), 63.f);
                o[i] = q * ss;
            }
            float4* p4 = reinterpret_cast<float4*>(
                &out[(((n * 3 + oc) * 256 + gy) << 8) + gx]);
            p4[0] = make_float4(o[0], o[1], o[2], o[3]);
            p4[1] = make_float4(o[4], o[5], o[6], o[7]);
        }
    }
}

// ---------------------------------------------------------------------------
extern "C" void kernel_launch(void* const* d_in, const int* in_sizes, int n_in,
                              void* d_out, int out_size)
{
    const float* x      = (const float*)d_in[0];
    const float* w1     = (const float*)d_in[1];
    const float* b1     = (const float*)d_in[2];
    const float* w2     = (const float*)d_in[3];
    const float* b2     = (const float*)d_in[4];
    const float* alpha1 = (const float*)d_in[5];
    const float* alpha2 = (const float*)d_in[6];
    const float* sw1    = (const float*)d_in[7];
    const float* sw2    = (const float*)d_in[8];
    const float* sa1    = (const float*)d_in[9];
    const float* sa2    = (const float*)d_in[10];
    float* out = (float*)d_out;

    cudaFuncSetAttribute(conv1_mma_kernel,
                         cudaFuncAttributeMaxDynamicSharedMemorySize, SMEM1);

    // captured ncu index == 3 (mod period): keep conv1 at index 3.
    prequant_kernel<<<(9 * 64 * 64 + 64 * 9 * 4 + 255) / 256, 256>>>(w1, sw1, w2, sw2);
    tick_kernel<<<1, 32>>>();
    tick_kernel<<<1, 32>>>();
    conv1_mma_kernel<<<NB * 256 * 2, 256, SMEM1>>>(x, sw1, b1, alpha1, sa1);
    conv2_kernel<<<NB * 32 * 2, 128>>>(b2, alpha2, sa2, out);
}

// round 16
// speedup vs baseline: 1.4413x; 1.0295x over previous
#include <cuda_runtime.h>
#include <cuda_fp16.h>
#include <cstdint>

// ---------------------------------------------------------------------------
// R16: conv1 = R15 byte-identical (best: 287us). conv2 redesigned: g_h stores
//      integer q as fp16 (exact), sa1 folded into conv2 weights in prequant,
//      CC2=8 (half the barriers). Accumulation ORDER unchanged everywhere.
//      Launch order puts conv2 at captured index 3 for its first profile.
// ---------------------------------------------------------------------------

#define IMG   256
#define NB    8
#define CIN   64

__device__ __half g_hq[NB * CIN * IMG * IMG];  // conv1 q (integer, exact fp16)
__device__ __half g_w1h[9 * 64 * 64];          // [tap][c][oc] linear
__device__ float  g_w2s[CIN * 9 * 4];          // w2q * sa1[c] folded

__device__ __forceinline__ uint32_t smem_u32(const void* p) {
    uint32_t a;
    asm("{ .reg .u64 t; cvta.to.shared.u64 t, %1; cvt.u32.u64 %0, t; }"
        : "=r"(a) : "l"(p));
    return a;
}
__device__ __forceinline__ void ldsm4(uint32_t* r, uint32_t addr) {
    asm volatile("ldmatrix.sync.aligned.m8n8.x4.shared.b16 {%0,%1,%2,%3}, [%4];"
        : "=r"(r[0]), "=r"(r[1]), "=r"(r[2]), "=r"(r[3]) : "r"(addr));
}
__device__ __forceinline__ void ldsm2t(uint32_t& r0, uint32_t& r1, uint32_t addr) {
    asm volatile("ldmatrix.sync.aligned.m8n8.x2.trans.shared.b16 {%0,%1}, [%2];"
        : "=r"(r0), "=r"(r1) : "r"(addr));
}
__device__ __forceinline__ void mma16816(float* c, const uint32_t* a, const uint32_t* b) {
    asm volatile("mma.sync.aligned.m16n8k16.row.col.f32.f16.f16.f32 "
        "{%0,%1,%2,%3}, {%4,%5,%6,%7}, {%8,%9}, {%0,%1,%2,%3};"
        : "+f"(c[0]), "+f"(c[1]), "+f"(c[2]), "+f"(c[3])
        : "r"(a[0]), "r"(a[1]), "r"(a[2]), "r"(a[3]), "r"(b[0]), "r"(b[1]));
}
__device__ __forceinline__ void cp16(uint32_t dst, const void* src) {
    asm volatile("cp.async.cg.shared.global [%0], [%1], 16;"
        :: "r"(dst), "l"(src));
}
#define CP_COMMIT() asm volatile("cp.async.commit_group;" ::: "memory")
#define CP_WAIT0()  asm volatile("cp.async.wait_group 0;"  ::: "memory")

// conv1 dynamic smem layout:
#define A_TERMB 18720u                 // 130 rows x 144B per split term
#define W_OFF   37440u
#define W_BUF   9216u
#define P_OFF   (W_OFF + 2u * W_BUF)   // 55872
#define SMEM1   (P_OFF + 1024u)        // 56896 -> occ 3 (170.7KB)

// ---------------- prequant (one-shot) ---------------------------------------
__global__ void prequant_kernel(const float* __restrict__ w1,
                                const float* __restrict__ sw1,
                                const float* __restrict__ w2,
                                const float* __restrict__ sw2,
                                const float* __restrict__ sa1)
{
    int idx = blockIdx.x * 256 + threadIdx.x;
    if (idx < 9 * 64 * 64) {
        int oc  = idx & 63;
        int c   = (idx >> 6) & 63;
        int tap = idx >> 12;
        float w = w1[(oc * 64 + c) * 9 + tap];
        float s = sw1[oc];
        float q = rintf(w / s);
        q = fminf(fmaxf(q, -64.f), 63.f);
        g_w1h[idx] = __float2half_rn(q);        // exact 7-bit integer
    } else if (idx < 9 * 64 * 64 + 64 * 9 * 4) {
        int j  = idx - 9 * 64 * 64;
        int oc = j & 3;
        int k  = j >> 2;            // c*9 + kk
        int c  = k / 9;
        int kk = k - c * 9;
        float v = 0.f;
        if (oc < 3) {
            float w = w2[(oc * CIN + c) * 9 + kk];
            float s = sw2[oc];
            float q = rintf(w / s);
            q = fminf(fmaxf(q, -64.f), 63.f);
            v = (q * s) * sa1[c];   // fold conv1 act scale into conv2 weight
        }
        g_w2s[j] = v;
    }
}

// tiny no-op launch: positions conv2 at captured index 3
__global__ void tick_kernel() {}

// ---------------- conv1: HMMA, occ 3, fast A-build (R15, byte-identical) ----
__global__ __launch_bounds__(256, 3)
void conv1_mma_kernel(const float* __restrict__ x,
                      const float* __restrict__ sw1,
                      const float* __restrict__ b1,
                      const float* __restrict__ alpha1,
                      const float* __restrict__ sa1)
{
    extern __shared__ unsigned char sm[];
    float* s_prm = (float*)(sm + P_OFF);
    const uint32_t sa_base = smem_u32(sm);
    const uint32_t sw_base = sa_base + W_OFF;

    const int tid  = threadIdx.x;
    const int lane = tid & 31;
    const int warp = tid >> 5;
    const int mrow = (warp & 3) * 32;
    const int ncol = (warp >> 2) * 32;

    const int bid = blockIdx.x;          // 8n * 256y * 2xt = 4096
    const int x0  = (bid & 1) * 128;
    const int y   = (bid >> 1) & 255;
    const int n   = bid >> 9;

    const int cp  = tid >> 3;            // channel pair 0..31
    const int jlo = tid & 7;

    {
        const char* src = (const char*)g_w1h;
        uint32_t dst = sw_base + (uint32_t)(tid >> 3) * 144u
                     + (uint32_t)(tid & 7) * 16u;
        cp16(dst, src + tid * 16);
        cp16(dst + (256 >> 3) * 144u, src + (tid + 256) * 16);
        CP_COMMIT();
    }

    if (tid < 256) {
        int a = tid >> 6, oc = tid & 63;
        const float* src = (a == 0) ? sw1 : (a == 1) ? b1 : (a == 2) ? alpha1 : sa1;
        s_prm[a * 64 + oc] = src[oc];
    }

    float acc[2][4][4];
    #pragma unroll
    for (int i = 0; i < 2; ++i)
        #pragma unroll
        for (int j = 0; j < 4; ++j)
            #pragma unroll
            for (int k = 0; k < 4; ++k) acc[i][j][k] = 0.f;

    const uint32_t arow  = lane & 15;
    const uint32_t ahalf = (lane >> 4) * 16;

    for (int s = 0; s < 3; ++s) {
        const int gy = y + s - 1;
        const bool row_ok = (unsigned)gy < 256u;
        if (s) __syncthreads();
        {
            const float* xc0 = x + (((n * 64 + 2 * cp) * 256 + gy) << 8) + x0 - 1;
            const float* xc1 = xc0 + 65536;
            #pragma unroll
            for (int it = 0; it < 17; ++it) {
                int j = jlo + (it << 3);
                if (j < 130) {
                    int gx = x0 - 1 + j;
                    float v0 = 0.f, v1 = 0.f;
                    if (row_ok && (unsigned)gx < 256u) { v0 = xc0[j]; v1 = xc1[j]; }
                    __half h0 = __float2half_rn(v0);
                    __half l0 = __float2half_rn(v0 - __half2float(h0));
                    __half h1 = __float2half_rn(v1);
                    __half l1 = __float2half_rn(v1 - __half2float(h1));
                    uint32_t hh = ((uint32_t)__half_as_ushort(h1) << 16)
                                |  (uint32_t)__half_as_ushort(h0);
                    uint32_t ll = ((uint32_t)__half_as_ushort(l1) << 16)
                                |  (uint32_t)__half_as_ushort(l0);
                    uint32_t off = (uint32_t)j * 144u + (uint32_t)cp * 4u;
                    *(uint32_t*)(sm + off)           = hh;
                    *(uint32_t*)(sm + A_TERMB + off) = ll;
                }
            }
        }

        for (int kw = 0; kw < 3; ++kw) {
            const int tap = s * 3 + kw;
            CP_WAIT0();
            __syncthreads();
            if (tap < 8) {
                const char* src = (const char*)g_w1h + (tap + 1) * 8192;
                uint32_t dst = sw_base + ((uint32_t)(tap + 1) & 1u) * W_BUF
                             + (uint32_t)(tid >> 3) * 144u
                             + (uint32_t)(tid & 7) * 16u;
                cp16(dst, src + tid * 16);
                cp16(dst + (256 >> 3) * 144u, src + (tid + 256) * 16);
                CP_COMMIT();
            }
            const uint32_t swb = sw_base + ((uint32_t)tap & 1u) * W_BUF;

            #pragma unroll
            for (int t = 0; t < 2; ++t) {
                #pragma unroll
                for (int k = 0; k < 4; ++k) {
                    uint32_t bf[4][2];
                    #pragma unroll
                    for (int nb = 0; nb < 4; ++nb)
                        ldsm2t(bf[nb][0], bf[nb][1],
                               swb + (uint32_t)(k * 16 + arow) * 144u
                                   + (uint32_t)(ncol + nb * 8) * 2u);
                    #pragma unroll
                    for (int mb = 0; mb < 2; ++mb) {
                        uint32_t af[4];
                        ldsm4(af, sa_base + (uint32_t)t * A_TERMB
                                 + (uint32_t)(mrow + mb * 16 + arow + kw) * 144u
                                 + ahalf + (uint32_t)k * 32u);
                        #pragma unroll
                        for (int nb = 0; nb < 4; ++nb)
                            mma16816(acc[mb][nb], af, bf[nb]);
                    }
                }
            }
        }
    }

    // ---- epilogue: same quant math; store integer q as fp16 (exact) --------
    #pragma unroll
    for (int mb = 0; mb < 2; ++mb)
        #pragma unroll
        for (int nb = 0; nb < 4; ++nb)
            #pragma unroll
            for (int rg = 0; rg < 4; ++rg) {
                int j  = mrow + mb * 16 + (lane >> 2) + (rg >> 1) * 8;
                int oc = ncol + nb * 8 + ((lane & 3) << 1) + (rg & 1);
                float v  = acc[mb][nb][rg] * s_prm[oc] + s_prm[64 + oc];
                float pv = (v >= 0.f) ? v : s_prm[128 + oc] * v;
                float ss = s_prm[192 + oc];
                float q  = rintf(pv / ss);
                q = fminf(fmaxf(q, -64.f), 63.f);
                g_hq[(((n * 64 + oc) * 256 + y) << 8) + x0 + j] = __float2half_rn(q);
            }
}

// ---------------- conv2: fp32 FFMA2, q inputs, CC2=8 ------------------------
#define TH2   8
#define T2W   128
#define CC2   8
#define P2R   10
#define P2CW  130
#define P2W   131

__global__ __launch_bounds__(128, 5)
void conv2_kernel(const float* __restrict__ b2,
                  const float* __restrict__ alpha2,
                  const float* __restrict__ sa2,
                  float* __restrict__ out)
{
    __shared__ __align__(16) float s_in[CC2 * P2R * P2W];   // 41.9 KB
    __shared__ __align__(16) float s_w2[CC2 * 9 * 4];       // 1.2 KB

    const int tid = threadIdx.x;
    const int bid = blockIdx.x;
    const int tx  = bid & 1;
    const int ty  = (bid >> 1) & 31;
    const int n   = bid >> 6;
    const int x0  = tx * T2W;
    const int y0  = ty * TH2;

    const int r    = tid & 7;
    const int g    = (tid >> 3) & 3;
    const int warp = tid >> 5;
    const int cb   = warp * 32 + g * 8;

    unsigned long long acc[2][8];
    #pragma unroll
    for (int i = 0; i < 2; ++i)
        #pragma unroll
        for (int j = 0; j < 8; ++j) acc[i][j] = 0ULL;

    for (int c0 = 0; c0 < CIN; c0 += CC2) {
        __syncthreads();
        for (int idx = tid; idx < CC2 * P2R * P2CW; idx += 128) {
            int c   = idx / (P2R * P2CW);
            int rem = idx - c * (P2R * P2CW);
            int row = rem / P2CW;
            int col = rem - row * P2CW;
            int gy  = y0 + row - 1;
            int gx  = x0 + col - 1;
            float v = 0.f;
            if ((unsigned)gy < 256u && (unsigned)gx < 256u)
                v = __half2float(g_hq[(((n * CIN + c0 + c) * 256 + gy) << 8) + gx]);
            s_in[(c * P2R + row) * P2W + col] = v;
        }
        for (int idx = tid; idx < CC2 * 9 * 4; idx += 128)
            s_w2[idx] = g_w2s[c0 * 9 * 4 + idx];
        __syncthreads();

        #pragma unroll 1
        for (int c = 0; c < CC2; ++c) {
            #pragma unroll
            for (int kh = 0; kh < 3; ++kh) {
                const float* rowp = &s_in[(c * P2R + r + kh) * P2W + cb];
                unsigned long long v2[10];
                #pragma unroll
                for (int i = 0; i < 10; ++i) {
                    unsigned int u = __float_as_uint(rowp[i]);
                    asm("mov.b64 %0, {%1, %1};" : "=l"(v2[i]) : "r"(u));
                }
                #pragma unroll
                for (int kw = 0; kw < 3; ++kw) {
                    const unsigned long long* wp = (const unsigned long long*)
                        &s_w2[((c0 ? 0 : 0) + c * 9 + kh * 3 + kw) << 2];
                    unsigned long long w0 = wp[0];
                    unsigned long long w1 = wp[1];
                    #pragma unroll
                    for (int px = 0; px < 8; ++px) {
                        asm("fma.rn.f32x2 %0, %1, %2, %0;"
                            : "+l"(acc[0][px]) : "l"(w0), "l"(v2[px + kw]));
                        asm("fma.rn.f32x2 %0, %1, %2, %0;"
                            : "+l"(acc[1][px]) : "l"(w1), "l"(v2[px + kw]));
                    }
                }
            }
        }
    }

    const int gy = y0 + r;
    const int gx = x0 + cb;
    #pragma unroll
    for (int cp = 0; cp < 2; ++cp) {
        float lo[8], hi[8];
        #pragma unroll
        for (int px = 0; px < 8; ++px) {
            unsigned int a, b;
            asm("mov.b64 {%0, %1}, %2;" : "=r"(a), "=r"(b) : "l"(acc[cp][px]));
            lo[px] = __uint_as_float(a);
            hi[px] = __uint_as_float(b);
        }
        #pragma unroll
        for (int half = 0; half < 2; ++half) {
            int oc = (cp << 1) + half;
            if (oc >= 3) continue;
            const float* v = half ? hi : lo;
            float bb = b2[oc], aa = alpha2[oc], ss = sa2[oc];
            float o[8];
            #pragma unroll
            for (int i = 0; i < 8; ++i) {
                float yv = v[i] + bb;
                float pv = (yv >= 0.f) ? yv : aa * yv;
                float q = rintf(pv / ss);
                q = fminf(fmaxf(q, -64.f), 63.f);
                o[i] = q * ss;
            }
            float4* p4 = reinterpret_cast<float4*>(
                &out[(((n * 3 + oc) * 256 + gy) << 8) + gx]);
            p4[0] = make_float4(o[0], o[1], o[2], o[3]);
            p4[1] = make_float4(o[4], o[5], o[6], o[7]);
        }
    }
}

// ---------------------------------------------------------------------------
extern "C" void kernel_launch(void* const* d_in, const int* in_sizes, int n_in,
                              void* d_out, int out_size)
{
    const float* x      = (const float*)d_in[0];
    const float* w1     = (const float*)d_in[1];
    const float* b1     = (const float*)d_in[2];
    const float* w2     = (const float*)d_in[3];
    const float* b2     = (const float*)d_in[4];
    const float* alpha1 = (const float*)d_in[5];
    const float* alpha2 = (const float*)d_in[6];
    const float* sw1    = (const float*)d_in[7];
    const float* sw2    = (const float*)d_in[8];
    const float* sa1    = (const float*)d_in[9];
    const float* sa2    = (const float*)d_in[10];
    float* out = (float*)d_out;

    cudaFuncSetAttribute(conv1_mma_kernel,
                         cudaFuncAttributeMaxDynamicSharedMemorySize, SMEM1);

    // captured ncu index == 3: prequant(0), conv1(1), tick(2), conv2(3)
    prequant_kernel<<<(9 * 64 * 64 + 64 * 9 * 4 + 255) / 256, 256>>>(w1, sw1, w2, sw2, sa1);
    conv1_mma_kernel<<<NB * 256 * 2, 256, SMEM1>>>(x, sw1, b1, alpha1, sa1);
    tick_kernel<<<1, 32>>>();
    conv2_kernel<<<NB * 32 * 2, 128>>>(b2, alpha2, sa2, out);
}

// round 17
// speedup vs baseline: 1.4836x; 1.0293x over previous
#include <cuda_runtime.h>
#include <cuda_fp16.h>
#include <cstdint>

// ---------------------------------------------------------------------------
// R17: conv1 = R15/R16 byte-identical (287us). conv2 rebalanced: 256 thr/blk,
//      4 px/thread (same tile, same per-pixel accumulation order => bitwise
//      identical results), occupancy ~2x. conv2 kept at ncu captured index 3.
// ---------------------------------------------------------------------------

#define IMG   256
#define NB    8
#define CIN   64

__device__ __half g_hq[NB * CIN * IMG * IMG];  // conv1 q (integer, exact fp16)
__device__ __half g_w1h[9 * 64 * 64];          // [tap][c][oc] linear
__device__ float  g_w2s[CIN * 9 * 4];          // w2q * sa1[c] folded

__device__ __forceinline__ uint32_t smem_u32(const void* p) {
    uint32_t a;
    asm("{ .reg .u64 t; cvta.to.shared.u64 t, %1; cvt.u32.u64 %0, t; }"
        : "=r"(a) : "l"(p));
    return a;
}
__device__ __forceinline__ void ldsm4(uint32_t* r, uint32_t addr) {
    asm volatile("ldmatrix.sync.aligned.m8n8.x4.shared.b16 {%0,%1,%2,%3}, [%4];"
        : "=r"(r[0]), "=r"(r[1]), "=r"(r[2]), "=r"(r[3]) : "r"(addr));
}
__device__ __forceinline__ void ldsm2t(uint32_t& r0, uint32_t& r1, uint32_t addr) {
    asm volatile("ldmatrix.sync.aligned.m8n8.x2.trans.shared.b16 {%0,%1}, [%2];"
        : "=r"(r0), "=r"(r1) : "r"(addr));
}
__device__ __forceinline__ void mma16816(float* c, const uint32_t* a, const uint32_t* b) {
    asm volatile("mma.sync.aligned.m16n8k16.row.col.f32.f16.f16.f32 "
        "{%0,%1,%2,%3}, {%4,%5,%6,%7}, {%8,%9}, {%0,%1,%2,%3};"
        : "+f"(c[0]), "+f"(c[1]), "+f"(c[2]), "+f"(c[3])
        : "r"(a[0]), "r"(a[1]), "r"(a[2]), "r"(a[3]), "r"(b[0]), "r"(b[1]));
}
__device__ __forceinline__ void cp16(uint32_t dst, const void* src) {
    asm volatile("cp.async.cg.shared.global [%0], [%1], 16;"
        :: "r"(dst), "l"(src));
}
#define CP_COMMIT() asm volatile("cp.async.commit_group;" ::: "memory")
#define CP_WAIT0()  asm volatile("cp.async.wait_group 0;"  ::: "memory")

// conv1 dynamic smem layout:
#define A_TERMB 18720u
#define W_OFF   37440u
#define W_BUF   9216u
#define P_OFF   (W_OFF + 2u * W_BUF)   // 55872
#define SMEM1   (P_OFF + 1024u)        // 56896 -> occ 3

// ---------------- prequant (one-shot) ---------------------------------------
__global__ void prequant_kernel(const float* __restrict__ w1,
                                const float* __restrict__ sw1,
                                const float* __restrict__ w2,
                                const float* __restrict__ sw2,
                                const float* __restrict__ sa1)
{
    int idx = blockIdx.x * 256 + threadIdx.x;
    if (idx < 9 * 64 * 64) {
        int oc  = idx & 63;
        int c   = (idx >> 6) & 63;
        int tap = idx >> 12;
        float w = w1[(oc * 64 + c) * 9 + tap];
        float s = sw1[oc];
        float q = rintf(w / s);
        q = fminf(fmaxf(q, -64.f), 63.f);
        g_w1h[idx] = __float2half_rn(q);
    } else if (idx < 9 * 64 * 64 + 64 * 9 * 4) {
        int j  = idx - 9 * 64 * 64;
        int oc = j & 3;
        int k  = j >> 2;
        int c  = k / 9;
        int kk = k - c * 9;
        float v = 0.f;
        if (oc < 3) {
            float w = w2[(oc * CIN + c) * 9 + kk];
            float s = sw2[oc];
            float q = rintf(w / s);
            q = fminf(fmaxf(q, -64.f), 63.f);
            v = (q * s) * sa1[c];
        }
        g_w2s[j] = v;
    }
}

// tiny no-op launch: positions conv2 at captured index 3
__global__ void tick_kernel() {}

// ---------------- conv1: HMMA, occ 3 (R15, byte-identical) ------------------
__global__ __launch_bounds__(256, 3)
void conv1_mma_kernel(const float* __restrict__ x,
                      const float* __restrict__ sw1,
                      const float* __restrict__ b1,
                      const float* __restrict__ alpha1,
                      const float* __restrict__ sa1)
{
    extern __shared__ unsigned char sm[];
    float* s_prm = (float*)(sm + P_OFF);
    const uint32_t sa_base = smem_u32(sm);
    const uint32_t sw_base = sa_base + W_OFF;

    const int tid  = threadIdx.x;
    const int lane = tid & 31;
    const int warp = tid >> 5;
    const int mrow = (warp & 3) * 32;
    const int ncol = (warp >> 2) * 32;

    const int bid = blockIdx.x;          // 8n * 256y * 2xt = 4096
    const int x0  = (bid & 1) * 128;
    const int y   = (bid >> 1) & 255;
    const int n   = bid >> 9;

    const int cp  = tid >> 3;
    const int jlo = tid & 7;

    {
        const char* src = (const char*)g_w1h;
        uint32_t dst = sw_base + (uint32_t)(tid >> 3) * 144u
                     + (uint32_t)(tid & 7) * 16u;
        cp16(dst, src + tid * 16);
        cp16(dst + (256 >> 3) * 144u, src + (tid + 256) * 16);
        CP_COMMIT();
    }

    if (tid < 256) {
        int a = tid >> 6, oc = tid & 63;
        const float* src = (a == 0) ? sw1 : (a == 1) ? b1 : (a == 2) ? alpha1 : sa1;
        s_prm[a * 64 + oc] = src[oc];
    }

    float acc[2][4][4];
    #pragma unroll
    for (int i = 0; i < 2; ++i)
        #pragma unroll
        for (int j = 0; j < 4; ++j)
            #pragma unroll
            for (int k = 0; k < 4; ++k) acc[i][j][k] = 0.f;

    const uint32_t arow  = lane & 15;
    const uint32_t ahalf = (lane >> 4) * 16;

    for (int s = 0; s < 3; ++s) {
        const int gy = y + s - 1;
        const bool row_ok = (unsigned)gy < 256u;
        if (s) __syncthreads();
        {
            const float* xc0 = x + (((n * 64 + 2 * cp) * 256 + gy) << 8) + x0 - 1;
            const float* xc1 = xc0 + 65536;
            #pragma unroll
            for (int it = 0; it < 17; ++it) {
                int j = jlo + (it << 3);
                if (j < 130) {
                    int gx = x0 - 1 + j;
                    float v0 = 0.f, v1 = 0.f;
                    if (row_ok && (unsigned)gx < 256u) { v0 = xc0[j]; v1 = xc1[j]; }
                    __half h0 = __float2half_rn(v0);
                    __half l0 = __float2half_rn(v0 - __half2float(h0));
                    __half h1 = __float2half_rn(v1);
                    __half l1 = __float2half_rn(v1 - __half2float(h1));
                    uint32_t hh = ((uint32_t)__half_as_ushort(h1) << 16)
                                |  (uint32_t)__half_as_ushort(h0);
                    uint32_t ll = ((uint32_t)__half_as_ushort(l1) << 16)
                                |  (uint32_t)__half_as_ushort(l0);
                    uint32_t off = (uint32_t)j * 144u + (uint32_t)cp * 4u;
                    *(uint32_t*)(sm + off)           = hh;
                    *(uint32_t*)(sm + A_TERMB + off) = ll;
                }
            }
        }

        for (int kw = 0; kw < 3; ++kw) {
            const int tap = s * 3 + kw;
            CP_WAIT0();
            __syncthreads();
            if (tap < 8) {
                const char* src = (const char*)g_w1h + (tap + 1) * 8192;
                uint32_t dst = sw_base + ((uint32_t)(tap + 1) & 1u) * W_BUF
                             + (uint32_t)(tid >> 3) * 144u
                             + (uint32_t)(tid & 7) * 16u;
                cp16(dst, src + tid * 16);
                cp16(dst + (256 >> 3) * 144u, src + (tid + 256) * 16);
                CP_COMMIT();
            }
            const uint32_t swb = sw_base + ((uint32_t)tap & 1u) * W_BUF;

            #pragma unroll
            for (int t = 0; t < 2; ++t) {
                #pragma unroll
                for (int k = 0; k < 4; ++k) {
                    uint32_t bf[4][2];
                    #pragma unroll
                    for (int nb = 0; nb < 4; ++nb)
                        ldsm2t(bf[nb][0], bf[nb][1],
                               swb + (uint32_t)(k * 16 + arow) * 144u
                                   + (uint32_t)(ncol + nb * 8) * 2u);
                    #pragma unroll
                    for (int mb = 0; mb < 2; ++mb) {
                        uint32_t af[4];
                        ldsm4(af, sa_base + (uint32_t)t * A_TERMB
                                 + (uint32_t)(mrow + mb * 16 + arow + kw) * 144u
                                 + ahalf + (uint32_t)k * 32u);
                        #pragma unroll
                        for (int nb = 0; nb < 4; ++nb)
                            mma16816(acc[mb][nb], af, bf[nb]);
                    }
                }
            }
        }
    }

    #pragma unroll
    for (int mb = 0; mb < 2; ++mb)
        #pragma unroll
        for (int nb = 0; nb < 4; ++nb)
            #pragma unroll
            for (int rg = 0; rg < 4; ++rg) {
                int j  = mrow + mb * 16 + (lane >> 2) + (rg >> 1) * 8;
                int oc = ncol + nb * 8 + ((lane & 3) << 1) + (rg & 1);
                float v  = acc[mb][nb][rg] * s_prm[oc] + s_prm[64 + oc];
                float pv = (v >= 0.f) ? v : s_prm[128 + oc] * v;
                float ss = s_prm[192 + oc];
                float q  = rintf(pv / ss);
                q = fminf(fmaxf(q, -64.f), 63.f);
                g_hq[(((n * 64 + oc) * 256 + y) << 8) + x0 + j] = __float2half_rn(q);
            }
}

// ---------------- conv2: fp32 FFMA2, 256 thr, 4 px/thread -------------------
#define TH2   8
#define T2W   128
#define CC2   8
#define P2R   10
#define P2CW  130
#define P2W   131

__global__ __launch_bounds__(256, 5)
void conv2_kernel(const float* __restrict__ b2,
                  const float* __restrict__ alpha2,
                  const float* __restrict__ sa2,
                  float* __restrict__ out)
{
    __shared__ __align__(16) float s_in[CC2 * P2R * P2W];   // 41.9 KB
    __shared__ __align__(16) float s_w2[CC2 * 9 * 4];       // 1.2 KB

    const int tid = threadIdx.x;
    const int bid = blockIdx.x;
    const int tx  = bid & 1;
    const int ty  = (bid >> 1) & 31;
    const int n   = bid >> 6;
    const int x0  = tx * T2W;
    const int y0  = ty * TH2;

    const int r   = tid & 7;
    const int grp = tid >> 3;            // 0..31
    const int cb  = grp * 4;             // 4 px per thread

    unsigned long long acc[2][4];
    #pragma unroll
    for (int i = 0; i < 2; ++i)
        #pragma unroll
        for (int j = 0; j < 4; ++j) acc[i][j] = 0ULL;

    for (int c0 = 0; c0 < CIN; c0 += CC2) {
        __syncthreads();
        for (int idx = tid; idx < CC2 * P2R * P2CW; idx += 256) {
            int c   = idx / (P2R * P2CW);
            int rem = idx - c * (P2R * P2CW);
            int row = rem / P2CW;
            int col = rem - row * P2CW;
            int gy  = y0 + row - 1;
            int gx  = x0 + col - 1;
            float v = 0.f;
            if ((unsigned)gy < 256u && (unsigned)gx < 256u)
                v = __half2float(g_hq[(((n * CIN + c0 + c) * 256 + gy) << 8) + gx]);
            s_in[(c * P2R + row) * P2W + col] = v;
        }
        for (int idx = tid; idx < CC2 * 9 * 4; idx += 256)
            s_w2[idx] = g_w2s[c0 * 9 * 4 + idx];
        __syncthreads();

        #pragma unroll 1
        for (int c = 0; c < CC2; ++c) {
            #pragma unroll
            for (int kh = 0; kh < 3; ++kh) {
                const float* rowp = &s_in[(c * P2R + r + kh) * P2W + cb];
                unsigned long long v2[6];
                #pragma unroll
                for (int i = 0; i < 6; ++i) {
                    unsigned int u = __float_as_uint(rowp[i]);
                    asm("mov.b64 %0, {%1, %1};" : "=l"(v2[i]) : "r"(u));
                }
                #pragma unroll
                for (int kw = 0; kw < 3; ++kw) {
                    const unsigned long long* wp = (const unsigned long long*)
                        &s_w2[(c * 9 + kh * 3 + kw) << 2];
                    unsigned long long w0 = wp[0];
                    unsigned long long w1 = wp[1];
                    #pragma unroll
                    for (int px = 0; px < 4; ++px) {
                        asm("fma.rn.f32x2 %0, %1, %2, %0;"
                            : "+l"(acc[0][px]) : "l"(w0), "l"(v2[px + kw]));
                        asm("fma.rn.f32x2 %0, %1, %2, %0;"
                            : "+l"(acc[1][px]) : "l"(w1), "l"(v2[px + kw]));
                    }
                }
            }
        }
    }

    const int gy = y0 + r;
    const int gx = x0 + cb;
    #pragma unroll
    for (int cp = 0; cp < 2; ++cp) {
        float lo[4], hi[4];
        #pragma unroll
        for (int px = 0; px < 4; ++px) {
            unsigned int a, b;
            asm("mov.b64 {%0, %1}, %2;" : "=r"(a), "=r"(b) : "l"(acc[cp][px]));
            lo[px] = __uint_as_float(a);
            hi[px] = __uint_as_float(b);
        }
        #pragma unroll
        for (int half = 0; half < 2; ++half) {
            int oc = (cp << 1) + half;
            if (oc >= 3) continue;
            const float* v = half ? hi : lo;
            float bb = b2[oc], aa = alpha2[oc], ss = sa2[oc];
            float o[4];
            #pragma unroll
            for (int i = 0; i < 4; ++i) {
                float yv = v[i] + bb;
                float pv = (yv >= 0.f) ? yv : aa * yv;
                float q = rintf(pv / ss);
                q = fminf(fmaxf(q, -64.f), 63.f);
                o[i] = q * ss;
            }
            *reinterpret_cast<float4*>(
                &out[(((n * 3 + oc) * 256 + gy) << 8) + gx]) =
                make_float4(o[0], o[1], o[2], o[3]);
        }
    }
}

// ---------------------------------------------------------------------------
extern "C" void kernel_launch(void* const* d_in, const int* in_sizes, int n_in,
                              void* d_out, int out_size)
{
    const float* x      = (const float*)d_in[0];
    const float* w1     = (const float*)d_in[1];
    const float* b1     = (const float*)d_in[2];
    const float* w2     = (const float*)d_in[3];
    const float* b2     = (const float*)d_in[4];
    const float* alpha1 = (const float*)d_in[5];
    const float* alpha2 = (const float*)d_in[6];
    const float* sw1    = (const float*)d_in[7];
    const float* sw2    = (const float*)d_in[8];
    const float* sa1    = (const float*)d_in[9];
    const float* sa2    = (const float*)d_in[10];
    float* out = (float*)d_out;

    cudaFuncSetAttribute(conv1_mma_kernel,
                         cudaFuncAttributeMaxDynamicSharedMemorySize, SMEM1);

    // captured ncu index == 3: prequant(0), conv1(1), tick(2), conv2(3)
    prequant_kernel<<<(9 * 64 * 64 + 64 * 9 * 4 + 255) / 256, 256>>>(w1, sw1, w2, sw2, sa1);
    conv1_mma_kernel<<<NB * 256 * 2, 256, SMEM1>>>(x, sw1, b1, alpha1, sa1);
    tick_kernel<<<1, 32>>>();
    conv2_kernel<<<NB * 32 * 2, 256>>>(b2, alpha2, sa2, out);
}